// round 1
// baseline (speedup 1.0000x reference)
#include <cuda_runtime.h>

// net_LSTM_21534966022336: single-layer bias-free LSTM, torch gate order (i,f,g,o)
// T=4096, B=8192, I=1, H=1  -> 8192 independent scalar LSTM chains.
// Latency-bound by the per-step nonlinear recurrence (~48 cyc/step).
// All sigmoids via one MUFU tanh each: sigmoid(z) = 0.5*tanh(z/2)+0.5,
// with pre-halved weights so z/2 comes out of the gate FMA directly.

#ifndef LSTM_T
#define LSTM_T 4096
#endif
#ifndef LSTM_B
#define LSTM_B 8192
#endif

__device__ __forceinline__ float tanh_approx(float v) {
    float y;
    asm("tanh.approx.f32 %0, %1;" : "=f"(y) : "f"(v));
    return y;
}

__global__ void __launch_bounds__(128, 1)
lstm_scalar_chain_kernel(const float* __restrict__ x,
                         const float* __restrict__ h0,
                         const float* __restrict__ c0,
                         const float* __restrict__ w_ih,
                         const float* __restrict__ w_hh,
                         float* __restrict__ out,
                         int out_size) {
    const int b = blockIdx.x * blockDim.x + threadIdx.x;
    if (b >= LSTM_B) return;

    // Shared scalar weights, gate order i, f, g, o.
    // Halve i/f/o weights so the gate FMA directly produces z/2 for sigmoid-via-tanh.
    const float wi_i = 0.5f * w_ih[0];
    const float wi_f = 0.5f * w_ih[1];
    const float wi_g =        w_ih[2];
    const float wi_o = 0.5f * w_ih[3];
    const float wh_i = 0.5f * w_hh[0];
    const float wh_f = 0.5f * w_hh[1];
    const float wh_g =        w_hh[2];
    const float wh_o = 0.5f * w_hh[3];

    float h = h0[b];
    float c = c0[b];

    constexpr int U = 8;
    float xb[U];

    // Preload first block of x values for this chain.
#pragma unroll
    for (int u = 0; u < U; ++u)
        xb[u] = x[u * LSTM_B + b];

    for (int t0 = 0; t0 < LSTM_T; t0 += U) {
        // Prefetch next block (off critical path, MLP = 8).
        float xn[U];
        const bool more = (t0 + U) < LSTM_T;
#pragma unroll
        for (int u = 0; u < U; ++u)
            xn[u] = more ? x[(t0 + U + u) * LSTM_B + b] : 0.0f;

#pragma unroll
        for (int u = 0; u < U; ++u) {
            const float xv = xb[u];
            // x-dependent terms: off the h->h critical path.
            const float xi = xv * wi_i;
            const float xf = xv * wi_f;
            const float xg = xv * wi_g;
            const float xo = xv * wi_o;

            const float ai = fmaf(h, wh_i, xi);   // = 0.5 * i_gate
            const float af = fmaf(h, wh_f, xf);   // = 0.5 * f_gate
            const float ag = fmaf(h, wh_g, xg);   // =       g_gate
            const float ao = fmaf(h, wh_o, xo);   // = 0.5 * o_gate

            const float ti = tanh_approx(ai);
            const float tf = tanh_approx(af);
            const float tg = tanh_approx(ag);
            const float to = tanh_approx(ao);

            const float si = fmaf(0.5f, ti, 0.5f);   // sigmoid(i_gate)
            const float sf = fmaf(0.5f, tf, 0.5f);   // sigmoid(f_gate)
            const float so = fmaf(0.5f, to, 0.5f);   // sigmoid(o_gate)

            c = fmaf(sf, c, si * tg);
            const float tc = tanh_approx(c);
            h = so * tc;

            out[(t0 + u) * LSTM_B + b] = h;       // fire-and-forget store
        }

#pragma unroll
        for (int u = 0; u < U; ++u)
            xb[u] = xn[u];
    }

    // h_n, c_n appended after out (tuple flattening order).
    if (out_size >= LSTM_T * LSTM_B + 2 * LSTM_B) {
        out[LSTM_T * LSTM_B + b]          = h;
        out[LSTM_T * LSTM_B + LSTM_B + b] = c;
    }
}

extern "C" void kernel_launch(void* const* d_in, const int* in_sizes, int n_in,
                              void* d_out, int out_size) {
    const float* x    = (const float*)d_in[0];
    const float* h0   = (const float*)d_in[1];
    const float* c0   = (const float*)d_in[2];
    const float* w_ih = (const float*)d_in[3];
    const float* w_hh = (const float*)d_in[4];
    float* out = (float*)d_out;

    // 8192 chains: 64 blocks x 128 threads -> one warp per SMSP on 64 SMs.
    const int threads = 128;
    const int blocks  = (LSTM_B + threads - 1) / threads;
    lstm_scalar_chain_kernel<<<blocks, threads>>>(x, h0, c0, w_ih, w_hh, out, out_size);
}

// round 2
// speedup vs baseline: 1.2738x; 1.2738x over previous
#include <cuda_runtime.h>

// net_LSTM_21534966022336: T=4096, B=8192, I=H=1 -> 8192 independent scalar
// LSTM chains. Wall time = 4096 * L where L = per-step critical path of one
// warp (latency + in-order issue). All optimization targets L.
//
// 2h formulation: track h2 = 2h, c = c.
//   half-preactivations for sigmoid gates (i,f,o): hz = (wi/2)x + (wh/4)h2
//   full preactivation for g:                      zg = wi*x + (wh/2)h2
//   t* = tanh(...) via MUFU; sigma(z) = (t+1)/2 absorbed:
//   p = fma(tf,c,c); q = fma(ti,tg,tg); c' = fma(0.5, p, 0.5*q)
//   tc = tanh(c'); h2' = fma(to, tc, tc); out h = 0.5*h2'

#ifndef LSTM_T
#define LSTM_T 4096
#endif
#ifndef LSTM_B
#define LSTM_B 8192
#endif

__device__ __forceinline__ float tanh_approx(float v) {
    float y;
    asm("tanh.approx.f32 %0, %1;" : "=f"(y) : "f"(v));
    return y;
}

__global__ void __launch_bounds__(128, 1)
lstm_scalar_chain_kernel(const float* __restrict__ x,
                         const float* __restrict__ h0,
                         const float* __restrict__ c0,
                         const float* __restrict__ w_ih,
                         const float* __restrict__ w_hh,
                         float* __restrict__ out,
                         int out_size) {
    const int b = blockIdx.x * blockDim.x + threadIdx.x;
    if (b >= LSTM_B) return;

    // Pre-scaled shared scalar weights (gate order i, f, g, o).
    const float wi_i = 0.50f * w_ih[0];
    const float wi_f = 0.50f * w_ih[1];
    const float wi_g =         w_ih[2];
    const float wi_o = 0.50f * w_ih[3];
    const float wh_i = 0.25f * w_hh[0];
    const float wh_f = 0.25f * w_hh[1];
    const float wh_g = 0.50f * w_hh[2];
    const float wh_o = 0.25f * w_hh[3];

    float h2 = 2.0f * h0[b];
    float c  = c0[b];

    const float* xp = x + b;
    float*       op = out + b;

    constexpr int U = 8;
    float xa[U], xb[U];

    // Preload steps 0..7 into xa, 8..15 into xb.
#pragma unroll
    for (int u = 0; u < U; ++u) xa[u] = xp[u * LSTM_B];
#pragma unroll
    for (int u = 0; u < U; ++u) xb[u] = xp[(U + u) * LSTM_B];

#define LSTM_STEP(xv_, t_)                                                 \
    {                                                                      \
        const float xv = (xv_);                                            \
        const float xg = xv * wi_g;                                        \
        const float xi = xv * wi_i;                                        \
        const float xf = xv * wi_f;                                        \
        const float xo = xv * wi_o;                                        \
        const float ag = fmaf(h2, wh_g, xg);                               \
        const float ai = fmaf(h2, wh_i, xi);                               \
        const float af = fmaf(h2, wh_f, xf);                               \
        const float ao = fmaf(h2, wh_o, xo);                               \
        const float tg = tanh_approx(ag);  /* MUFU order: g first */       \
        const float ti = tanh_approx(ai);                                  \
        const float tf = tanh_approx(af);                                  \
        const float to = tanh_approx(ao);  /* o last: consumed last */     \
        const float q  = fmaf(ti, tg, tg); /* 2*sigmoid(i)*tanh(g) */      \
        const float hq = 0.5f * q;                                         \
        const float p  = fmaf(tf, c, c);   /* 2*sigmoid(f)*c */            \
        c = fmaf(0.5f, p, hq);                                             \
        const float tc = tanh_approx(c);                                   \
        h2 = fmaf(to, tc, tc);             /* 2*sigmoid(o)*tanh(c) */      \
        op[(t_) * LSTM_B] = 0.5f * h2;                                     \
    }

    for (int t0 = 0; t0 < LSTM_T; t0 += 2 * U) {
        // Prefetch steps t0+16..t0+23 into xa's successor slot is xa itself:
        // process xa (t0..t0+7) while loading the block after xb.
        float xn0[U];
#pragma unroll
        for (int u = 0; u < U; ++u) {
            int t = t0 + 2 * U + u;
            t = (t < LSTM_T) ? t : (LSTM_T - 1);   // clamp: safe dummy load
            xn0[u] = xp[t * LSTM_B];
        }
#pragma unroll
        for (int u = 0; u < U; ++u) LSTM_STEP(xa[u], t0 + u)
#pragma unroll
        for (int u = 0; u < U; ++u) xa[u] = xn0[u];

        // Prefetch steps t0+24..t0+31 while processing xb (t0+8..t0+15).
        float xn1[U];
#pragma unroll
        for (int u = 0; u < U; ++u) {
            int t = t0 + 3 * U + u;
            t = (t < LSTM_T) ? t : (LSTM_T - 1);
            xn1[u] = xp[t * LSTM_B];
        }
#pragma unroll
        for (int u = 0; u < U; ++u) LSTM_STEP(xb[u], t0 + U + u)
#pragma unroll
        for (int u = 0; u < U; ++u) xb[u] = xn1[u];
    }
#undef LSTM_STEP

    // h_n, c_n appended after out (tuple flattening order).
    if (out_size >= LSTM_T * LSTM_B + 2 * LSTM_B) {
        out[LSTM_T * LSTM_B + b]          = 0.5f * h2;
        out[LSTM_T * LSTM_B + LSTM_B + b] = c;
    }
}

extern "C" void kernel_launch(void* const* d_in, const int* in_sizes, int n_in,
                              void* d_out, int out_size) {
    const float* x    = (const float*)d_in[0];
    const float* h0   = (const float*)d_in[1];
    const float* c0   = (const float*)d_in[2];
    const float* w_ih = (const float*)d_in[3];
    const float* w_hh = (const float*)d_in[4];
    float* out = (float*)d_out;

    const int threads = 128;
    const int blocks  = (LSTM_B + threads - 1) / threads;
    lstm_scalar_chain_kernel<<<blocks, threads>>>(x, h0, c0, w_ih, w_hh, out, out_size);
}

// round 4
// speedup vs baseline: 1.6614x; 1.3043x over previous
#include <cuda_runtime.h>

// net_LSTM_21534966022336: T=4096, B=8192, I=H=1 -> 8192 independent scalar
// LSTM chains; latency-bound by the per-step serial recurrence.
//
// State carried as (tc, to, c) where tc = tanh(c_t), to = tanh(o_half_t):
//   h2 = 2h = tc*(1+to)  is never materialized on the critical path.
//   Gate half/full preactivations: a_* = fma(tc, s_*, x_*) with
//   s_* = fma(to, wh_*, wh_*)  (computed during the tanh(c) wait).
// Sigmoids via one MUFU tanh each with pre-scaled weights.

#ifndef LSTM_T
#define LSTM_T 4096
#endif
#ifndef LSTM_B
#define LSTM_B 8192
#endif

__device__ __forceinline__ float tanh_approx(float v) {
    float y;
    asm("tanh.approx.f32 %0, %1;" : "=f"(y) : "f"(v));
    return y;
}

__global__ void __launch_bounds__(128, 1)
lstm_scalar_chain_kernel(const float* __restrict__ x,
                         const float* __restrict__ h0,
                         const float* __restrict__ c0,
                         const float* __restrict__ w_ih,
                         const float* __restrict__ w_hh,
                         float* __restrict__ out,
                         int out_size) {
    const int b = blockIdx.x * blockDim.x + threadIdx.x;
    if (b >= LSTM_B) return;

    // Pre-scaled shared scalar weights (gate order i, f, g, o).
    // i/f/o sigmoid gates use half-preactivations (sigmoid(z)=0.5*tanh(z/2)+0.5),
    // and the recurrent input is h2 = 2h, hence the 0.25 factors.
    const float wi_i = 0.50f * w_ih[0];
    const float wi_f = 0.50f * w_ih[1];
    const float wi_g =         w_ih[2];
    const float wi_o = 0.50f * w_ih[3];
    const float wh_i = 0.25f * w_hh[0];
    const float wh_f = 0.25f * w_hh[1];
    const float wh_g = 0.50f * w_hh[2];
    const float wh_o = 0.25f * w_hh[3];

    // Seed: tc*(1+to) must equal 2*h0  ->  tc = 2*h0, to = 0 (exact).
    float tc = 2.0f * h0[b];
    float to = 0.0f;
    float c  = c0[b];

    const float* xp = x + b;
    float*       op = out + b;

    // 4-phase ring of 8-wide x buffers: 32 steps resident, each phase's
    // buffer reloaded in place right after consumption (prefetch dist = 24).
    float xr[32];
#pragma unroll
    for (int u = 0; u < 32; ++u) xr[u] = xp[u * LSTM_B];

    for (int t0 = 0; t0 < LSTM_T; t0 += 32) {
#pragma unroll
        for (int ph = 0; ph < 4; ++ph) {
#pragma unroll
            for (int u = 0; u < 8; ++u) {
                const int t = t0 + ph * 8 + u;
                const float xv = xr[ph * 8 + u];

                // x terms: independent, schedulable into any wait.
                const float xg = xv * wi_g;
                const float xi = xv * wi_i;
                const float xf = xv * wi_f;
                const float xo = xv * wi_o;

                // s_* depend only on `to` (ready before tc): hide in tanh(c) wait.
                const float sg = fmaf(to, wh_g, wh_g);
                const float si = fmaf(to, wh_i, wh_i);
                const float sf = fmaf(to, wh_f, wh_f);
                const float so = fmaf(to, wh_o, wh_o);

                // One FFMA after tc lands, then straight into MUFU.
                const float ag = fmaf(tc, sg, xg);
                const float ai = fmaf(tc, si, xi);
                const float af = fmaf(tc, sf, xf);
                const float ao = fmaf(tc, so, xo);

                const float tg  = tanh_approx(ag);   // needed 1st (q)
                const float ti  = tanh_approx(ai);   // needed 1st (q)
                const float tf  = tanh_approx(af);   // needed 2nd (p)
                const float to2 = tanh_approx(ao);   // needed last

                const float q  = fmaf(ti, tg, tg);   // 2*sigmoid(i)*tanh(g)
                const float hq = 0.5f * q;
                const float p  = fmaf(tf, c, c);     // 2*sigmoid(f)*c
                c = fmaf(0.5f, p, hq);

                const float tc2 = tanh_approx(c);

                // Output h = sigmoid(o)*tanh(c) = tc2 * (0.5 + 0.5*to2); off-path.
                const float sho = fmaf(to2, 0.5f, 0.5f);
                op[t * LSTM_B] = tc2 * sho;

                tc = tc2;
                to = to2;
            }
            // Reload this phase's buffer for t0+32 (clamped dummy at the tail).
#pragma unroll
            for (int u = 0; u < 8; ++u) {
                int t = t0 + 32 + ph * 8 + u;
                t = (t < LSTM_T) ? t : (LSTM_T - 1);
                xr[ph * 8 + u] = xp[t * LSTM_B];
            }
        }
    }

    // h_n, c_n appended after out (tuple flattening order).
    if (out_size >= LSTM_T * LSTM_B + 2 * LSTM_B) {
        out[LSTM_T * LSTM_B + b]          = tc * fmaf(to, 0.5f, 0.5f);
        out[LSTM_T * LSTM_B + LSTM_B + b] = c;
    }
}

extern "C" void kernel_launch(void* const* d_in, const int* in_sizes, int n_in,
                              void* d_out, int out_size) {
    const float* x    = (const float*)d_in[0];
    const float* h0   = (const float*)d_in[1];
    const float* c0   = (const float*)d_in[2];
    const float* w_ih = (const float*)d_in[3];
    const float* w_hh = (const float*)d_in[4];
    float* out = (float*)d_out;

    const int threads = 128;
    const int blocks  = (LSTM_B + threads - 1) / threads;
    lstm_scalar_chain_kernel<<<blocks, threads>>>(x, h0, c0, w_ih, w_hh, out, out_size);
}

// round 5
// speedup vs baseline: 1.7845x; 1.0741x over previous
#include <cuda_runtime.h>

// net_LSTM_21534966022336: T=4096, B=8192, I=H=1 -> 8192 independent scalar
// LSTM chains; latency-bound: wall = 4096 * L (per-step serial path).
//
// State carried as (tc, to, c), tc = tanh(c_t), to = tanh(o_half_t):
//   h2 = 2h = tc*(1+to) never materialized; gate preacts a_* = fma(tc,s_*,x_*)
//   with s_* = fma(to, wh_*, wh_*) hidden in the tanh(c) wait.
// c-update re-associated so the last critical MUFU (ti) feeds ONE fma:
//   c' = fma(tf,hc,hc) + htg + ti*htg,  hc=c/2, htg=tg/2
//   -> v = fma(tf,hc,hc); s = v + htg; c' = fma(ti, htg, s)
// MUFU issue order f, g, i (critical), then o (off-path).

#ifndef LSTM_T
#define LSTM_T 4096
#endif
#ifndef LSTM_B
#define LSTM_B 8192
#endif

__device__ __forceinline__ float tanh_approx(float v) {
    float y;
    asm("tanh.approx.f32 %0, %1;" : "=f"(y) : "f"(v));
    return y;
}

__global__ void __launch_bounds__(128, 1)
lstm_scalar_chain_kernel(const float* __restrict__ x,
                         const float* __restrict__ h0,
                         const float* __restrict__ c0,
                         const float* __restrict__ w_ih,
                         const float* __restrict__ w_hh,
                         float* __restrict__ out,
                         int out_size) {
    const int b = blockIdx.x * blockDim.x + threadIdx.x;
    if (b >= LSTM_B) return;

    // Pre-scaled shared scalar weights (gate order i, f, g, o).
    const float wi_i = 0.50f * w_ih[0];
    const float wi_f = 0.50f * w_ih[1];
    const float wi_g =         w_ih[2];
    const float wi_o = 0.50f * w_ih[3];
    const float wh_i = 0.25f * w_hh[0];
    const float wh_f = 0.25f * w_hh[1];
    const float wh_g = 0.50f * w_hh[2];
    const float wh_o = 0.25f * w_hh[3];

    // Seed: tc*(1+to) = 2*h0  ->  tc = 2*h0, to = 0 (exact).
    float tc = 2.0f * h0[b];
    float to = 0.0f;
    float c  = c0[b];

    const float* xp = x + b;
    float*       op = out + b;

    // 4-phase ring of 8-wide x buffers: 32 steps resident, reloaded in place
    // right after consumption (prefetch distance = 24 steps, no copies).
    float xr[32];
#pragma unroll
    for (int u = 0; u < 32; ++u) xr[u] = xp[u * LSTM_B];

    for (int t0 = 0; t0 < LSTM_T; t0 += 32) {
#pragma unroll
        for (int ph = 0; ph < 4; ++ph) {
#pragma unroll
            for (int u = 0; u < 8; ++u) {
                const int t = t0 + ph * 8 + u;
                const float xv = xr[ph * 8 + u];

                // Off-path terms: x projections + to-dependent recurrent scales
                // (to lands well before tc) + hc from previous c.
                const float xf = xv * wi_f;
                const float xg = xv * wi_g;
                const float xi = xv * wi_i;
                const float xo = xv * wi_o;

                const float sf = fmaf(to, wh_f, wh_f);
                const float sg = fmaf(to, wh_g, wh_g);
                const float si = fmaf(to, wh_i, wh_i);
                const float so = fmaf(to, wh_o, wh_o);

                const float hc = 0.5f * c;

                // One FFMA after tc lands, straight into MUFU (order f,g,i,o).
                const float af = fmaf(tc, sf, xf);
                const float ag = fmaf(tc, sg, xg);
                const float ai = fmaf(tc, si, xi);
                const float ao = fmaf(tc, so, xo);

                const float tf  = tanh_approx(af);   // 1st: feeds v earliest
                const float tg  = tanh_approx(ag);   // 2nd: feeds htg
                const float ti  = tanh_approx(ai);   // 3rd: terminal fma
                const float to2 = tanh_approx(ao);   // off-path

                const float v   = fmaf(tf, hc, hc);      // 2*sigmoid(f)*c / 2
                const float htg = 0.5f * tg;
                const float s   = v + htg;
                c = fmaf(ti, htg, s);                    // c'

                const float tc2 = tanh_approx(c);

                // h = sigmoid(o)*tanh(c) = tc2*(0.5 + 0.5*to2); off-path.
                const float sho = fmaf(to2, 0.5f, 0.5f);
                op[t * LSTM_B] = tc2 * sho;

                tc = tc2;
                to = to2;
            }
            // Reload this phase's buffer for t0+32 (clamped dummy at tail).
#pragma unroll
            for (int u = 0; u < 8; ++u) {
                int t = t0 + 32 + ph * 8 + u;
                t = (t < LSTM_T) ? t : (LSTM_T - 1);
                xr[ph * 8 + u] = xp[t * LSTM_B];
            }
        }
    }

    // h_n, c_n appended after out (tuple flattening order).
    if (out_size >= LSTM_T * LSTM_B + 2 * LSTM_B) {
        out[LSTM_T * LSTM_B + b]          = tc * fmaf(to, 0.5f, 0.5f);
        out[LSTM_T * LSTM_B + LSTM_B + b] = c;
    }
}

extern "C" void kernel_launch(void* const* d_in, const int* in_sizes, int n_in,
                              void* d_out, int out_size) {
    const float* x    = (const float*)d_in[0];
    const float* h0   = (const float*)d_in[1];
    const float* c0   = (const float*)d_in[2];
    const float* w_ih = (const float*)d_in[3];
    const float* w_hh = (const float*)d_in[4];
    float* out = (float*)d_out;

    const int threads = 128;
    const int blocks  = (LSTM_B + threads - 1) / threads;
    lstm_scalar_chain_kernel<<<blocks, threads>>>(x, h0, c0, w_ih, w_hh, out, out_size);
}